// round 13
// baseline (speedup 1.0000x reference)
#include <cuda_runtime.h>
#include <cstdint>

// Problem constants: input (64, 65536, 6) f32, output (64, 640) f32.
#define BATCHES     64
#define POINTS      65536
#define PAIRS       (POINTS / 2)            // 32768 pairs per batch
#define PAIRS_TOTAL (BATCHES * PAIRS)       // 2097152
#define F4_PER_B    (POINTS * 6 / 4)        // 98304 float4 per batch
#define NUM_BINS    4
#define NUM_CELLS   64
#define STATS       10
#define FEAT        (NUM_CELLS * STATS)     // 640

// Kernel 1 (bbox) config — R3 strided config (best measured: 18.6us).
#define BPB1        32
#define T1          256
#define PAIRS_PER_BLK1 (PAIRS / BPB1)       // 1024
#define ITER1       (PAIRS_PER_BLK1 / T1)   // 4

// Kernel 2 (accumulate): flat balanced grid, 3 blocks/SM, 2 histogram
// segments (a block's pair range spans at most 2 batches).
#define GRID2       444                     // 148 SMs x 3 — perfectly balanced
#define T2          512
#define PPB         ((PAIRS_TOTAL + GRID2 - 1) / GRID2)   // 4724
#define ITER2       ((PPB + T2 - 1) / T2)   // 10
#define REPL        8                       // smem replicas (lane & 7)
#define SEG_WORDS   (FEAT * REPL)           // 5120 floats = 20 KB per segment
#define HIST_WORDS  (2 * SEG_WORDS)         // 10240 floats = 40 KB
#define HIST_BYTES  (HIST_WORDS * 4)

// Device scratch (zero at module load; k_final restores zeros after each use
// so every graph replay sees identical initial state).
__device__ unsigned int g_bbox[BATCHES];
__device__ float        g_sums[BATCHES * FEAT];

// ---------------------------------------------------------------------------
// Kernel 1: per-batch bbox_max = max(|pos|), strided pair loads (R3-exact).
// Layout per point pair (12 floats = 3 float4):
//   a = [p0x p0y p0z o0x]  b = [o0y o0z p1x p1y]  c = [p1z o1x o1y o1z]
// ---------------------------------------------------------------------------
__global__ __launch_bounds__(T1) void k_bbox(const float4* __restrict__ in4) {
    const int batch = blockIdx.y;
    const int tid = threadIdx.x;
    const float4* p = in4 + (size_t)batch * F4_PER_B;
    const int base = blockIdx.x * PAIRS_PER_BLK1;

    float m = 0.0f;
#pragma unroll
    for (int k = 0; k < ITER1; k++) {
        int j = base + tid + k * T1;
        float4 a = p[3 * j + 0];
        float4 b = p[3 * j + 1];
        float4 c = p[3 * j + 2];
        m = fmaxf(m, fmaxf(fmaxf(fabsf(a.x), fabsf(a.y)), fabsf(a.z)));
        m = fmaxf(m, fmaxf(fmaxf(fabsf(b.z), fabsf(b.w)), fabsf(c.x)));
    }
#pragma unroll
    for (int o = 16; o > 0; o >>= 1)
        m = fmaxf(m, __shfl_xor_sync(0xFFFFFFFFu, m, o));

    __shared__ float sm[T1 / 32];
    if ((tid & 31) == 0) sm[tid >> 5] = m;
    __syncthreads();
    if (tid == 0) {
        float mm = sm[0];
#pragma unroll
        for (int i = 1; i < T1 / 32; i++) mm = fmaxf(mm, sm[i]);
        atomicMax(&g_bbox[batch], __float_as_uint(mm));  // positive floats
        cudaTriggerProgrammaticLaunchCompletion();
    }
}

// ---------------------------------------------------------------------------
// Kernel 2: flat-grid bin + accumulate.
// Each block owns pairs [s, e) of the GLOBAL pair range (may span 2 batches).
// Histogram: hist[seg][feat][REPL], seg 0 = first batch, seg 1 = second.
// Word addr = (seg*FEAT + feat)*8 + (lane&7).
// ---------------------------------------------------------------------------
extern __shared__ float hist[];   // HIST_WORDS floats (40 KB dynamic)

__device__ __forceinline__ void accum_point(
    float* __restrict__ h,   // segment base + (lane&7)
    float px, float py, float pz,
    float ox, float oy, float oz,
    float bbox, float inv)
{
    float picx = (px + bbox) * inv;
    float picy = (py + bbox) * inv;
    float picz = (pz + bbox) * inv;
    int ix = (int)(picx * 4.0f); ix = min(max(ix, 0), 3);
    int iy = (int)(picy * 4.0f); iy = min(max(iy, 0), 3);
    int iz = (int)(picz * 4.0f); iz = min(max(iz, 0), 3);
    int cell = (ix * NUM_BINS + iy) * NUM_BINS + iz;
    float* d = h + cell * (STATS * REPL);
    atomicAdd(d + 0 * REPL, 1.0f);
    atomicAdd(d + 1 * REPL, picx);
    atomicAdd(d + 2 * REPL, picy);
    atomicAdd(d + 3 * REPL, picz);
    atomicAdd(d + 4 * REPL, ox * ox);
    atomicAdd(d + 5 * REPL, ox * oy);
    atomicAdd(d + 6 * REPL, ox * oz);
    atomicAdd(d + 7 * REPL, oy * oy);
    atomicAdd(d + 8 * REPL, oy * oz);
    atomicAdd(d + 9 * REPL, oz * oz);
}

__global__ __launch_bounds__(T2, 3) void k_accum(const float4* __restrict__ in4) {
    const int tid = threadIdx.x;
    const int lane = tid & 31;
    const int rep = lane & (REPL - 1);

    // PDL preamble: zero histogram before waiting on k_bbox.
    float4* h4 = (float4*)hist;
#pragma unroll
    for (int i = tid; i < HIST_WORDS / 4; i += T2)
        h4[i] = make_float4(0.f, 0.f, 0.f, 0.f);

    // Block's global pair range [s, e); boundary splits the two batches.
    const int s = blockIdx.x * PPB;
    const int e = min(s + PPB, PAIRS_TOTAL);
    const int b0 = s / PAIRS;                        // first batch
    const int bnd = min(e, (b0 + 1) * PAIRS);        // end of b0's pairs
    const int b1 = min(b0 + 1, BATCHES - 1);         // second batch (may be unused)

    cudaGridDependencySynchronize();   // wait: k_bbox complete + visible
    __syncthreads();

    const float bb0 = __uint_as_float(g_bbox[b0]);
    const float bb1 = __uint_as_float(g_bbox[b1]);
    const float inv0 = 1.0f / fmaxf(2.0f * bb0, 1e-5f);
    const float inv1 = 1.0f / fmaxf(2.0f * bb1, 1e-5f);

    float* h0 = hist + rep;              // segment 0
    float* h1 = hist + SEG_WORDS + rep;  // segment 1

#pragma unroll
    for (int k = 0; k < ITER2; k++) {
        int j = s + tid + k * T2;
        if (j < e) {
            bool seg1 = (j >= bnd);
            float bb = seg1 ? bb1 : bb0;
            float inv = seg1 ? inv1 : inv0;
            float* h = seg1 ? h1 : h0;
            const float4* p = in4 + (size_t)3 * j;
            float4 a = p[0];
            float4 b = p[1];
            float4 c = p[2];
            accum_point(h, a.x, a.y, a.z, a.w, b.x, b.y, bb, inv);
            accum_point(h, b.z, b.w, c.x, c.y, c.z, c.w, bb, inv);
        }
    }
    __syncthreads();

    // Flush both segments (segment 1 is all zeros if the block didn't cross
    // a batch boundary — adding zeros to b1 is harmless).
    for (int idx = tid; idx < 2 * FEAT; idx += T2) {
        int seg = idx / FEAT;
        int w = idx - seg * FEAT;
        int batch = seg ? b1 : b0;
        float sum = 0.0f;
#pragma unroll
        for (int r = 0; r < REPL; r++)
            sum += hist[(seg * FEAT + w) * REPL + ((r + lane) & (REPL - 1))];
        atomicAdd(&g_sums[batch * FEAT + w], sum);
    }
    __syncthreads();
    if (tid == 0) cudaTriggerProgrammaticLaunchCompletion();
}

// ---------------------------------------------------------------------------
// Kernel 3: finalize. One block per batch, 640 threads = one (cell, stat).
// L2-normalize the 640-vector; restore scratch to zero for next replay.
// ---------------------------------------------------------------------------
__global__ __launch_bounds__(FEAT) void k_final(float* __restrict__ out) {
    cudaGridDependencySynchronize();   // wait: k_accum complete + visible

    const int b = blockIdx.x;
    const int t = threadIdx.x;               // 0..639
    const int cell = t / STATS;
    const int s = t - cell * STATS;

    float* sums = g_sums + b * FEAT;
    float cnt = sums[cell * STATS];
    float val = sums[t];
    float fc = fmaxf(cnt, 1.0f);
    float up = rsqrtf(fc);

    float f;
    if (s == 0) {
        f = 0.001f * cnt * up;
    } else if (s < 4) {
        int d = s - 1;
        int ci = (d == 0) ? (cell >> 4) : (d == 1) ? ((cell >> 2) & 3) : (cell & 3);
        float g = ((float)ci + 0.5f) * 0.25f;
        f = (val - cnt * g) * up;
    } else {
        f = val / fc;
    }

    float q = f * f;
#pragma unroll
    for (int o = 16; o > 0; o >>= 1)
        q += __shfl_xor_sync(0xFFFFFFFFu, q, o);

    __shared__ float wsum[FEAT / 32];
    __shared__ float s_inv;
    if ((t & 31) == 0) wsum[t >> 5] = q;
    __syncthreads();

    // all reads of g_sums done -> restore zeros for the next replay
    sums[t] = 0.0f;
    if (t == 0) {
        g_bbox[b] = 0u;
        float ss = 0.0f;
#pragma unroll
        for (int i = 0; i < FEAT / 32; i++) ss += wsum[i];
        s_inv = 1.0f / fmaxf(sqrtf(ss), 1e-12f);
    }
    __syncthreads();

    out[b * FEAT + t] = f * s_inv;
}

// ---------------------------------------------------------------------------
extern "C" void kernel_launch(void* const* d_in, const int* in_sizes, int n_in,
                              void* d_out, int out_size) {
    const float4* in4 = (const float4*)d_in[0];
    float* out = (float*)d_out;
    (void)in_sizes; (void)n_in; (void)out_size;

    cudaFuncSetAttribute(k_accum, cudaFuncAttributeMaxDynamicSharedMemorySize,
                         HIST_BYTES);

    // k_bbox: normal launch (producer).
    k_bbox<<<dim3(BPB1, BATCHES), T1>>>(in4);

    // k_accum: programmatic dependent launch on k_bbox.
    {
        cudaLaunchAttribute a[1];
        a[0].id = cudaLaunchAttributeProgrammaticStreamSerialization;
        a[0].val.programmaticStreamSerializationAllowed = 1;
        cudaLaunchConfig_t cfg{};
        cfg.gridDim = dim3(GRID2);
        cfg.blockDim = dim3(T2);
        cfg.dynamicSmemBytes = HIST_BYTES;
        cfg.stream = 0;
        cfg.attrs = a;
        cfg.numAttrs = 1;
        cudaLaunchKernelEx(&cfg, k_accum, in4);
    }

    // k_final: programmatic dependent launch on k_accum.
    {
        cudaLaunchAttribute a[1];
        a[0].id = cudaLaunchAttributeProgrammaticStreamSerialization;
        a[0].val.programmaticStreamSerializationAllowed = 1;
        cudaLaunchConfig_t cfg{};
        cfg.gridDim = dim3(BATCHES);
        cfg.blockDim = dim3(FEAT);
        cfg.dynamicSmemBytes = 0;
        cfg.stream = 0;
        cfg.attrs = a;
        cfg.numAttrs = 1;
        cudaLaunchKernelEx(&cfg, k_final, out);
    }
}

// round 14
// speedup vs baseline: 2.0976x; 2.0976x over previous
#include <cuda_runtime.h>
#include <cstdint>

// Problem constants: input (64, 65536, 6) f32, output (64, 640) f32.
#define BATCHES     64
#define POINTS      65536
#define PAIRS       (POINTS / 2)            // 32768 pairs per batch
#define PAIRS_TOTAL (BATCHES * PAIRS)       // 2097152
#define F4_PER_B    (POINTS * 6 / 4)        // 98304 float4 per batch
#define NUM_BINS    4
#define NUM_CELLS   64
#define STATS       10
#define FEAT        (NUM_CELLS * STATS)     // 640

// Kernel 1 (bbox) config — R3 strided config (best measured: ~18.6us).
#define BPB1        32
#define T1          256
#define PAIRS_PER_BLK1 (PAIRS / BPB1)       // 1024
#define ITER1       (PAIRS_PER_BLK1 / T1)   // 4

// Kernel 2 (accumulate): flat balanced grid, REPL=32 (conflict-free, proven),
// batch-boundary crossing handled temporally (flush + re-zero).
#define GRID2       296                     // 148 SMs x 2 — perfectly balanced
#define T2          512
#define PPB         ((PAIRS_TOTAL + GRID2 - 1) / GRID2)   // 7085
#define REPL        32                      // one replica per lane — required!
#define HIST_WORDS  (FEAT * REPL)           // 20480 floats = 80 KB
#define HIST_BYTES  (HIST_WORDS * 4)

// Device scratch (zero at module load; k_final restores zeros after each use
// so every graph replay sees identical initial state).
__device__ unsigned int g_bbox[BATCHES];
__device__ float        g_sums[BATCHES * FEAT];

// ---------------------------------------------------------------------------
// Kernel 1: per-batch bbox_max = max(|pos|), strided pair loads (R3-exact).
// Layout per point pair (12 floats = 3 float4):
//   a = [p0x p0y p0z o0x]  b = [o0y o0z p1x p1y]  c = [p1z o1x o1y o1z]
// ---------------------------------------------------------------------------
__global__ __launch_bounds__(T1) void k_bbox(const float4* __restrict__ in4) {
    const int batch = blockIdx.y;
    const int tid = threadIdx.x;
    const float4* p = in4 + (size_t)batch * F4_PER_B;
    const int base = blockIdx.x * PAIRS_PER_BLK1;

    float m = 0.0f;
#pragma unroll
    for (int k = 0; k < ITER1; k++) {
        int j = base + tid + k * T1;
        float4 a = p[3 * j + 0];
        float4 b = p[3 * j + 1];
        float4 c = p[3 * j + 2];
        m = fmaxf(m, fmaxf(fmaxf(fabsf(a.x), fabsf(a.y)), fabsf(a.z)));
        m = fmaxf(m, fmaxf(fmaxf(fabsf(b.z), fabsf(b.w)), fabsf(c.x)));
    }
#pragma unroll
    for (int o = 16; o > 0; o >>= 1)
        m = fmaxf(m, __shfl_xor_sync(0xFFFFFFFFu, m, o));

    __shared__ float sm[T1 / 32];
    if ((tid & 31) == 0) sm[tid >> 5] = m;
    __syncthreads();
    if (tid == 0) {
        float mm = sm[0];
#pragma unroll
        for (int i = 1; i < T1 / 32; i++) mm = fmaxf(mm, sm[i]);
        atomicMax(&g_bbox[batch], __float_as_uint(mm));  // positive floats
        cudaTriggerProgrammaticLaunchCompletion();
    }
}

// ---------------------------------------------------------------------------
// Kernel 2: flat-grid bin + accumulate, REPL=32 per-lane replicas.
// Word addr = (cell*10 + s)*32 + lane  ->  bank == lane, conflict-free and
// same-address-free within a warp.
// ---------------------------------------------------------------------------
extern __shared__ float hist[];   // HIST_WORDS floats (80 KB dynamic)

__device__ __forceinline__ void accum_point(
    float* __restrict__ h,   // hist + lane
    float px, float py, float pz,
    float ox, float oy, float oz,
    float bbox, float inv)
{
    float picx = (px + bbox) * inv;
    float picy = (py + bbox) * inv;
    float picz = (pz + bbox) * inv;
    int ix = (int)(picx * 4.0f); ix = min(max(ix, 0), 3);
    int iy = (int)(picy * 4.0f); iy = min(max(iy, 0), 3);
    int iz = (int)(picz * 4.0f); iz = min(max(iz, 0), 3);
    int cell = (ix * NUM_BINS + iy) * NUM_BINS + iz;
    float* d = h + cell * (STATS * REPL);
    atomicAdd(d + 0 * REPL, 1.0f);
    atomicAdd(d + 1 * REPL, picx);
    atomicAdd(d + 2 * REPL, picy);
    atomicAdd(d + 3 * REPL, picz);
    atomicAdd(d + 4 * REPL, ox * ox);
    atomicAdd(d + 5 * REPL, ox * oy);
    atomicAdd(d + 6 * REPL, ox * oz);
    atomicAdd(d + 7 * REPL, oy * oy);
    atomicAdd(d + 8 * REPL, oy * oz);
    atomicAdd(d + 9 * REPL, oz * oz);
}

// Process global pair range [lo, hi) for one batch, accumulate into hist.
__device__ __forceinline__ void accum_range(
    const float4* __restrict__ in4, int lo, int hi,
    float bbox, float inv, float* hrep, int tid)
{
    for (int j = lo + tid; j < hi; j += T2) {
        const float4* p = in4 + (size_t)3 * j;
        float4 a = p[0];
        float4 b = p[1];
        float4 c = p[2];
        accum_point(hrep, a.x, a.y, a.z, a.w, b.x, b.y, bbox, inv);
        accum_point(hrep, b.z, b.w, c.x, c.y, c.z, c.w, bbox, inv);
    }
}

// Reduce 32 replicas per feature (rotated reads -> 32 distinct banks) and
// flush to g_sums[batch].
__device__ __forceinline__ void flush_hist(int batch, int tid, int lane) {
    for (int w = tid; w < FEAT; w += T2) {
        float s = 0.0f;
#pragma unroll
        for (int r = 0; r < REPL; r++)
            s += hist[w * REPL + ((r + lane) & 31)];
        atomicAdd(&g_sums[batch * FEAT + w], s);
    }
}

__global__ __launch_bounds__(T2, 2) void k_accum(const float4* __restrict__ in4) {
    const int tid = threadIdx.x;
    const int lane = tid & 31;

    // PDL preamble: zero histogram before waiting on k_bbox.
    float4* h4 = (float4*)hist;
#pragma unroll
    for (int i = tid; i < HIST_WORDS / 4; i += T2)
        h4[i] = make_float4(0.f, 0.f, 0.f, 0.f);

    // Block's global pair range [s, e); may span two batches.
    const int s = blockIdx.x * PPB;
    const int e = min(s + PPB, PAIRS_TOTAL);
    const int b0 = s / PAIRS;
    const int bnd = min(e, (b0 + 1) * PAIRS);   // end of b0's pairs

    cudaGridDependencySynchronize();   // wait: k_bbox complete + visible
    __syncthreads();

    float* hrep = hist + lane;

    // ---- phase 1: batch b0 ----
    {
        const float bb = __uint_as_float(g_bbox[b0]);
        const float inv = 1.0f / fmaxf(2.0f * bb, 1e-5f);
        accum_range(in4, s, bnd, bb, inv, hrep, tid);
        __syncthreads();
        flush_hist(b0, tid, lane);
    }

    // ---- phase 2: batch b0+1 (only the 63 boundary-crossing blocks) ----
    if (bnd < e) {
        __syncthreads();
        // re-zero histogram
#pragma unroll
        for (int i = tid; i < HIST_WORDS / 4; i += T2)
            h4[i] = make_float4(0.f, 0.f, 0.f, 0.f);
        __syncthreads();

        const int b1 = b0 + 1;
        const float bb = __uint_as_float(g_bbox[b1]);
        const float inv = 1.0f / fmaxf(2.0f * bb, 1e-5f);
        accum_range(in4, bnd, e, bb, inv, hrep, tid);
        __syncthreads();
        flush_hist(b1, tid, lane);
    }

    __syncthreads();
    if (tid == 0) cudaTriggerProgrammaticLaunchCompletion();
}

// ---------------------------------------------------------------------------
// Kernel 3: finalize. One block per batch, 640 threads = one (cell, stat).
// L2-normalize the 640-vector; restore scratch to zero for next replay.
// ---------------------------------------------------------------------------
__global__ __launch_bounds__(FEAT) void k_final(float* __restrict__ out) {
    cudaGridDependencySynchronize();   // wait: k_accum complete + visible

    const int b = blockIdx.x;
    const int t = threadIdx.x;               // 0..639
    const int cell = t / STATS;
    const int s = t - cell * STATS;

    float* sums = g_sums + b * FEAT;
    float cnt = sums[cell * STATS];
    float val = sums[t];
    float fc = fmaxf(cnt, 1.0f);
    float up = rsqrtf(fc);

    float f;
    if (s == 0) {
        f = 0.001f * cnt * up;
    } else if (s < 4) {
        int d = s - 1;
        int ci = (d == 0) ? (cell >> 4) : (d == 1) ? ((cell >> 2) & 3) : (cell & 3);
        float g = ((float)ci + 0.5f) * 0.25f;
        f = (val - cnt * g) * up;
    } else {
        f = val / fc;
    }

    float q = f * f;
#pragma unroll
    for (int o = 16; o > 0; o >>= 1)
        q += __shfl_xor_sync(0xFFFFFFFFu, q, o);

    __shared__ float wsum[FEAT / 32];
    __shared__ float s_inv;
    if ((t & 31) == 0) wsum[t >> 5] = q;
    __syncthreads();

    // all reads of g_sums done -> restore zeros for the next replay
    sums[t] = 0.0f;
    if (t == 0) {
        g_bbox[b] = 0u;
        float ss = 0.0f;
#pragma unroll
        for (int i = 0; i < FEAT / 32; i++) ss += wsum[i];
        s_inv = 1.0f / fmaxf(sqrtf(ss), 1e-12f);
    }
    __syncthreads();

    out[b * FEAT + t] = f * s_inv;
}

// ---------------------------------------------------------------------------
extern "C" void kernel_launch(void* const* d_in, const int* in_sizes, int n_in,
                              void* d_out, int out_size) {
    const float4* in4 = (const float4*)d_in[0];
    float* out = (float*)d_out;
    (void)in_sizes; (void)n_in; (void)out_size;

    cudaFuncSetAttribute(k_accum, cudaFuncAttributeMaxDynamicSharedMemorySize,
                         HIST_BYTES);

    // k_bbox: normal launch (producer).
    k_bbox<<<dim3(BPB1, BATCHES), T1>>>(in4);

    // k_accum: programmatic dependent launch on k_bbox.
    {
        cudaLaunchAttribute a[1];
        a[0].id = cudaLaunchAttributeProgrammaticStreamSerialization;
        a[0].val.programmaticStreamSerializationAllowed = 1;
        cudaLaunchConfig_t cfg{};
        cfg.gridDim = dim3(GRID2);
        cfg.blockDim = dim3(T2);
        cfg.dynamicSmemBytes = HIST_BYTES;
        cfg.stream = 0;
        cfg.attrs = a;
        cfg.numAttrs = 1;
        cudaLaunchKernelEx(&cfg, k_accum, in4);
    }

    // k_final: programmatic dependent launch on k_accum.
    {
        cudaLaunchAttribute a[1];
        a[0].id = cudaLaunchAttributeProgrammaticStreamSerialization;
        a[0].val.programmaticStreamSerializationAllowed = 1;
        cudaLaunchConfig_t cfg{};
        cfg.gridDim = dim3(BATCHES);
        cfg.blockDim = dim3(FEAT);
        cfg.dynamicSmemBytes = 0;
        cfg.stream = 0;
        cfg.attrs = a;
        cfg.numAttrs = 1;
        cudaLaunchKernelEx(&cfg, k_final, out);
    }
}